// round 5
// baseline (speedup 1.0000x reference)
#include <cuda_runtime.h>
#include <cstdint>

#define NN 1000000
#define NE 16000000

#define NBUCK   512                         // allocated buckets (pow2)
#define BSHIFT  11                          // 2048 nodes per bucket
#define BNODES  2048
#define NB_USED ((NN + BNODES - 1) / BNODES)   // 489 used buckets
#define NCTA_SORT 2048
#define CHUNK   ((NE + NCTA_SORT - 1) / NCTA_SORT)  // 7813
#define SPLIT   4                           // CTAs per bucket in bucketed passes

// ---- scratch (device globals; no allocations allowed) ----
__device__ int    g_deg[NN];
__device__ float  g_dis[NN];
__device__ float  g_u[NN];
__device__ float  g_acc1[NN];
__device__ float2 g_t[NN];
__device__ float2 g_acc2[NN];

__device__ unsigned long long g_bedges[NE];      // bucketed (col<<32 | row)
__device__ int g_cnt[NBUCK * NCTA_SORT];         // [bucket][cta] counts -> offsets
__device__ int g_btot[NBUCK];
__device__ int g_bbase[NBUCK];

// ---- no-return global reductions ----
__device__ __forceinline__ void red_add_u32v(int* addr, int v) {
    asm volatile("red.global.add.u32 [%0], %1;" :: "l"(addr), "r"(v) : "memory");
}
__device__ __forceinline__ void red_add_f32(float* addr, float v) {
    asm volatile("red.global.add.f32 [%0], %1;" :: "l"(addr), "f"(v) : "memory");
}
__device__ __forceinline__ void red_add_v2(float2* addr, float2 v) {
    asm volatile("red.global.add.v2.f32 [%0], {%1, %2};"
                 :: "l"(addr), "f"(v.x), "f"(v.y) : "memory");
}

// ---------------------------------------------------------------------------
// zero the degree array
__global__ __launch_bounds__(256) void k_zero() {
    int i = blockIdx.x * blockDim.x + threadIdx.x;
    if (i < NN) g_deg[i] = 0;
}

// per-(CTA, bucket) histogram of col
__global__ __launch_bounds__(256) void k_count(const int* __restrict__ col, int E) {
    __shared__ int scnt[NBUCK];
    for (int j = threadIdx.x; j < NBUCK; j += 256) scnt[j] = 0;
    __syncthreads();
    int start = blockIdx.x * CHUNK;
    int end   = min(start + CHUNK, E);
    for (int i = start + threadIdx.x; i < end; i += 256)
        atomicAdd(&scnt[((unsigned)col[i]) >> BSHIFT], 1);
    __syncthreads();
    for (int b = threadIdx.x; b < NBUCK; b += 256)
        g_cnt[b * NCTA_SORT + blockIdx.x] = scnt[b];
}

// exclusive scan of each bucket's 2048 per-CTA counts (in place); totals to g_btot
__global__ __launch_bounds__(256) void k_scan() {
    __shared__ int part[256];
    int b = blockIdx.x;
    int* rowp = &g_cnt[b * NCTA_SORT];
    int base = threadIdx.x * 8;
    int v[8];
    int s = 0;
#pragma unroll
    for (int k = 0; k < 8; k++) { v[k] = rowp[base + k]; s += v[k]; }
    part[threadIdx.x] = s;
    __syncthreads();
    for (int off = 1; off < 256; off <<= 1) {
        int t = (threadIdx.x >= off) ? part[threadIdx.x - off] : 0;
        __syncthreads();
        part[threadIdx.x] += t;
        __syncthreads();
    }
    int run = part[threadIdx.x] - s;   // exclusive prefix of this thread
#pragma unroll
    for (int k = 0; k < 8; k++) { int tmp = v[k]; rowp[base + k] = run; run += tmp; }
    if (threadIdx.x == 255) g_btot[b] = run;
}

// exclusive scan of bucket totals -> bucket bases
__global__ __launch_bounds__(512) void k_base() {
    __shared__ int part[512];
    int v = g_btot[threadIdx.x];
    part[threadIdx.x] = v;
    __syncthreads();
    for (int off = 1; off < 512; off <<= 1) {
        int t = (threadIdx.x >= off) ? part[threadIdx.x - off] : 0;
        __syncthreads();
        part[threadIdx.x] += t;
        __syncthreads();
    }
    g_bbase[threadIdx.x] = part[threadIdx.x] - v;
}

// scatter edges into bucket-sorted staging array
__global__ __launch_bounds__(256) void k_sort(const int* __restrict__ row,
                                              const int* __restrict__ col, int E) {
    __shared__ int scur[NBUCK];
    for (int b = threadIdx.x; b < NBUCK; b += 256)
        scur[b] = g_bbase[b] + g_cnt[b * NCTA_SORT + blockIdx.x];
    __syncthreads();
    int start = blockIdx.x * CHUNK;
    int end   = min(start + CHUNK, E);
    for (int i = start + threadIdx.x; i < end; i += 256) {
        unsigned r = (unsigned)row[i];
        unsigned c = (unsigned)col[i];
        int slot = atomicAdd(&scur[c >> BSHIFT], 1);
        g_bedges[slot] = ((unsigned long long)c << 32) | r;
    }
}

// bucketed degree count: smem histogram + coalesced global reduction
__global__ __launch_bounds__(256) void k_degp() {
    __shared__ int sdeg[BNODES];
    int b = blockIdx.x / SPLIT, q = blockIdx.x % SPLIT;
    for (int j = threadIdx.x; j < BNODES; j += 256) sdeg[j] = 0;
    __syncthreads();
    int bs = g_bbase[b], len = g_btot[b];
    int qs = bs + (int)((long long)len * q / SPLIT);
    int qe = bs + (int)((long long)len * (q + 1) / SPLIT);
    for (int i = qs + threadIdx.x; i < qe; i += 256) {
        unsigned c = (unsigned)(__ldcs(&g_bedges[i]) >> 32);
        atomicAdd(&sdeg[c & (BNODES - 1)], 1);
    }
    __syncthreads();
    int node0 = b << BSHIFT;
    for (int j = threadIdx.x; j < BNODES; j += 256) {
        int n = node0 + j;
        int v = sdeg[j];
        if (n < NN && v) red_add_u32v(&g_deg[n], v);
    }
}

// dis = rsqrt(deg + 1); u = dis * x; zero acc1
__global__ __launch_bounds__(256) void k_prep(const float* __restrict__ x) {
    int i = blockIdx.x * blockDim.x + threadIdx.x;
    if (i < NN) {
        float d = rsqrtf((float)(g_deg[i] + 1));
        g_dis[i]  = d;
        g_u[i]    = d * x[i];
        g_acc1[i] = 0.0f;
    }
}

// layer-1 bucketed scatter: gather u[row] (random), smem-accumulate, coalesced red
__global__ __launch_bounds__(256) void k_scat1_b() {
    __shared__ float sacc[BNODES];
    int b = blockIdx.x / SPLIT, q = blockIdx.x % SPLIT;
    for (int j = threadIdx.x; j < BNODES; j += 256) sacc[j] = 0.0f;
    __syncthreads();
    int bs = g_bbase[b], len = g_btot[b];
    int qs = bs + (int)((long long)len * q / SPLIT);
    int qe = bs + (int)((long long)len * (q + 1) / SPLIT);
    for (int i = qs + threadIdx.x; i < qe; i += 256) {
        unsigned long long e = __ldcs(&g_bedges[i]);
        unsigned r = (unsigned)e;
        unsigned c = (unsigned)(e >> 32);
        float v = __ldg(&g_u[r]);
        atomicAdd(&sacc[c & (BNODES - 1)], v);
    }
    __syncthreads();
    int node0 = b << BSHIFT;
    for (int j = threadIdx.x; j < BNODES; j += 256) {
        int n = node0 + j;
        float v = sacc[j];
        if (n < NN && v != 0.0f) red_add_f32(&g_acc1[n], v);
    }
}

// per-node MLP: s -> relu(W1*s+b1) -> @W2 ; t = dis * g; zero acc2
__global__ __launch_bounds__(256) void k_node2(const float4* __restrict__ W1,
                                               const float4* __restrict__ b1,
                                               const float4* __restrict__ W2) {
    int i = blockIdx.x * blockDim.x + threadIdx.x;
    if (i >= NN) return;
    float d = g_dis[i];
    float s = d * (g_acc1[i] + g_u[i]);
    float g0 = 0.0f, g1 = 0.0f;
#pragma unroll
    for (int q = 0; q < 4; q++) {
        float4 w1 = __ldg(&W1[q]);
        float4 bb = __ldg(&b1[q]);
        float4 e0 = __ldg(&W2[2 * q]);
        float4 e1 = __ldg(&W2[2 * q + 1]);
        float h0 = fmaxf(fmaf(s, w1.x, bb.x), 0.0f);
        float h1 = fmaxf(fmaf(s, w1.y, bb.y), 0.0f);
        float h2 = fmaxf(fmaf(s, w1.z, bb.z), 0.0f);
        float h3 = fmaxf(fmaf(s, w1.w, bb.w), 0.0f);
        g0 = fmaf(h0, e0.x, g0); g1 = fmaf(h0, e0.y, g1);
        g0 = fmaf(h1, e0.z, g0); g1 = fmaf(h1, e0.w, g1);
        g0 = fmaf(h2, e1.x, g0); g1 = fmaf(h2, e1.y, g1);
        g0 = fmaf(h3, e1.z, g0); g1 = fmaf(h3, e1.w, g1);
    }
    g_t[i]    = make_float2(d * g0, d * g1);
    g_acc2[i] = make_float2(0.0f, 0.0f);
}

// layer-2 bucketed scatter: gather t[row] (random), smem float2 acc, coalesced red
__global__ __launch_bounds__(256) void k_scat2_b() {
    __shared__ float sacc[BNODES * 2];
    int b = blockIdx.x / SPLIT, q = blockIdx.x % SPLIT;
    for (int j = threadIdx.x; j < BNODES * 2; j += 256) sacc[j] = 0.0f;
    __syncthreads();
    int bs = g_bbase[b], len = g_btot[b];
    int qs = bs + (int)((long long)len * q / SPLIT);
    int qe = bs + (int)((long long)len * (q + 1) / SPLIT);
    for (int i = qs + threadIdx.x; i < qe; i += 256) {
        unsigned long long e = __ldcs(&g_bedges[i]);
        unsigned r = (unsigned)e;
        unsigned c = (unsigned)(e >> 32);
        float2 t = __ldg(&g_t[r]);
        int j = (int)(c & (BNODES - 1)) * 2;
        atomicAdd(&sacc[j],     t.x);
        atomicAdd(&sacc[j + 1], t.y);
    }
    __syncthreads();
    int node0 = b << BSHIFT;
    for (int j = threadIdx.x; j < BNODES; j += 256) {
        int n = node0 + j;
        float vx = sacc[j * 2], vy = sacc[j * 2 + 1];
        if (n < NN && (vx != 0.0f || vy != 0.0f))
            red_add_v2(&g_acc2[n], make_float2(vx, vy));
    }
}

// final: out = dis*(acc2 + t) + b2, then log_softmax over 2 classes
__global__ __launch_bounds__(256) void k_out(const float* __restrict__ b2,
                                             float2* __restrict__ out) {
    int i = blockIdx.x * blockDim.x + threadIdx.x;
    if (i >= NN) return;
    float d  = g_dis[i];
    float2 a = g_acc2[i];
    float2 t = g_t[i];
    float b20 = __ldg(&b2[0]);
    float b21 = __ldg(&b2[1]);
    float o0 = fmaf(d, a.x + t.x, b20);
    float o1 = fmaf(d, a.y + t.y, b21);
    float m  = fmaxf(o0, o1);
    float lse = m + log1pf(__expf(fminf(o0, o1) - m));
    out[i] = make_float2(o0 - lse, o1 - lse);
}

// ---------------------------------------------------------------------------
extern "C" void kernel_launch(void* const* d_in, const int* in_sizes, int n_in,
                              void* d_out, int out_size) {
    const float* x   = (const float*)d_in[0];
    const int*   ei  = (const int*)d_in[1];
    const float* W1  = (const float*)d_in[2];
    const float* b1  = (const float*)d_in[3];
    const float* W2  = (const float*)d_in[4];
    const float* b2  = (const float*)d_in[5];
    float2* out = (float2*)d_out;

    const int E = in_sizes[1] / 2;      // edge_index is [2, E]
    const int* row = ei;                // source
    const int* col = ei + E;            // target

    const int TB = 256;
    const int nodeBlocks = (NN + TB - 1) / TB;
    const int buckBlocks = NB_USED * SPLIT;

    k_zero   <<<nodeBlocks, TB>>>();
    k_count  <<<NCTA_SORT, TB>>>(col, E);
    k_scan   <<<NBUCK, TB>>>();
    k_base   <<<1, 512>>>();
    k_sort   <<<NCTA_SORT, TB>>>(row, col, E);
    k_degp   <<<buckBlocks, TB>>>();
    k_prep   <<<nodeBlocks, TB>>>(x);
    k_scat1_b<<<buckBlocks, TB>>>();
    k_node2  <<<nodeBlocks, TB>>>((const float4*)W1, (const float4*)b1,
                                  (const float4*)W2);
    k_scat2_b<<<buckBlocks, TB>>>();
    k_out    <<<nodeBlocks, TB>>>(b2, out);
}

// round 6
// speedup vs baseline: 1.4315x; 1.4315x over previous
#include <cuda_runtime.h>
#include <cstdint>

#define NN 1000000
#define NE 16000000

// ---- scratch (device globals; no allocations allowed) ----
__device__ int    g_deg[NN];
__device__ float  g_dis[NN];
__device__ float  g_u[NN];
__device__ float  g_acc1[NN];
__device__ float2 g_t[NN];
__device__ float2 g_acc2[NN];

// ---- no-return global reductions ----
__device__ __forceinline__ void red_add_u32(int* addr) {
    asm volatile("red.global.add.u32 [%0], 1;" :: "l"(addr) : "memory");
}
__device__ __forceinline__ void red_add_f32(float* addr, float v) {
    asm volatile("red.global.add.f32 [%0], %1;" :: "l"(addr), "f"(v) : "memory");
}
__device__ __forceinline__ void red_add_v2(float2* addr, float2 v) {
    asm volatile("red.global.add.v2.f32 [%0], {%1, %2};"
                 :: "l"(addr), "f"(v.x), "f"(v.y) : "memory");
}

// ---------------------------------------------------------------------------
// zero the degree array; 4 nodes/thread, vector store
__global__ __launch_bounds__(256) void k_zero() {
    int i = blockIdx.x * blockDim.x + threadIdx.x;
    if (i < NN / 4)
        reinterpret_cast<int4*>(g_deg)[i] = make_int4(0, 0, 0, 0);
}

// degree count over target (col) indices; 4 edges per thread
__global__ __launch_bounds__(256) void k_deg(const int* __restrict__ col, int E) {
    int i = (blockIdx.x * blockDim.x + threadIdx.x) * 4;
    if (i + 3 < E) {
        int4 c = __ldcs(reinterpret_cast<const int4*>(col + i));
        red_add_u32(&g_deg[c.x]);
        red_add_u32(&g_deg[c.y]);
        red_add_u32(&g_deg[c.z]);
        red_add_u32(&g_deg[c.w]);
    }
}

// dis = rsqrt(deg + 1 self-loop); u = dis * x; zero acc1.  4 nodes/thread.
__global__ __launch_bounds__(256) void k_prep(const float4* __restrict__ x4) {
    int i = blockIdx.x * blockDim.x + threadIdx.x;
    if (i >= NN / 4) return;
    int4   dg = reinterpret_cast<const int4*>(g_deg)[i];
    float4 xv = __ldg(&x4[i]);
    float4 d;
    d.x = rsqrtf((float)(dg.x + 1));
    d.y = rsqrtf((float)(dg.y + 1));
    d.z = rsqrtf((float)(dg.z + 1));
    d.w = rsqrtf((float)(dg.w + 1));
    float4 u = make_float4(d.x * xv.x, d.y * xv.y, d.z * xv.z, d.w * xv.w);
    reinterpret_cast<float4*>(g_dis)[i]  = d;
    reinterpret_cast<float4*>(g_u)[i]    = u;
    reinterpret_cast<float4*>(g_acc1)[i] = make_float4(0.f, 0.f, 0.f, 0.f);
}

// scatter layer-1 messages: acc1[col] += u[row]; 4 edges per thread
__global__ __launch_bounds__(256) void k_scat1(const int* __restrict__ row,
                                               const int* __restrict__ col, int E) {
    int i = (blockIdx.x * blockDim.x + threadIdx.x) * 4;
    if (i + 3 < E) {
        int4 r = __ldcs(reinterpret_cast<const int4*>(row + i));
        int4 c = __ldcs(reinterpret_cast<const int4*>(col + i));
        float u0 = __ldg(&g_u[r.x]);
        float u1 = __ldg(&g_u[r.y]);
        float u2 = __ldg(&g_u[r.z]);
        float u3 = __ldg(&g_u[r.w]);
        red_add_f32(&g_acc1[c.x], u0);
        red_add_f32(&g_acc1[c.y], u1);
        red_add_f32(&g_acc1[c.z], u2);
        red_add_f32(&g_acc1[c.w], u3);
    }
}

// per-node MLP, 2 nodes/thread: s -> relu(W1*s+b1) -> @W2 ; t = dis*g; zero acc2
__device__ __forceinline__ void mlp2(float s, const float4* w1q, const float4* bbq,
                                     const float4* e0q, const float4* e1q,
                                     float& g0, float& g1) {
    g0 = 0.0f; g1 = 0.0f;
#pragma unroll
    for (int q = 0; q < 4; q++) {
        float h0 = fmaxf(fmaf(s, w1q[q].x, bbq[q].x), 0.0f);
        float h1 = fmaxf(fmaf(s, w1q[q].y, bbq[q].y), 0.0f);
        float h2 = fmaxf(fmaf(s, w1q[q].z, bbq[q].z), 0.0f);
        float h3 = fmaxf(fmaf(s, w1q[q].w, bbq[q].w), 0.0f);
        g0 = fmaf(h0, e0q[q].x, g0); g1 = fmaf(h0, e0q[q].y, g1);
        g0 = fmaf(h1, e0q[q].z, g0); g1 = fmaf(h1, e0q[q].w, g1);
        g0 = fmaf(h2, e1q[q].x, g0); g1 = fmaf(h2, e1q[q].y, g1);
        g0 = fmaf(h3, e1q[q].z, g0); g1 = fmaf(h3, e1q[q].w, g1);
    }
}

__global__ __launch_bounds__(256) void k_node2(const float4* __restrict__ W1,
                                               const float4* __restrict__ b1,
                                               const float4* __restrict__ W2) {
    int i = blockIdx.x * blockDim.x + threadIdx.x;
    if (i >= NN / 2) return;
    float4 w1q[4], bbq[4], e0q[4], e1q[4];
#pragma unroll
    for (int q = 0; q < 4; q++) {
        w1q[q] = __ldg(&W1[q]);
        bbq[q] = __ldg(&b1[q]);
        e0q[q] = __ldg(&W2[2 * q]);
        e1q[q] = __ldg(&W2[2 * q + 1]);
    }
    float2 d  = reinterpret_cast<const float2*>(g_dis)[i];
    float2 a  = reinterpret_cast<const float2*>(g_acc1)[i];
    float2 uu = reinterpret_cast<const float2*>(g_u)[i];
    float s0 = d.x * (a.x + uu.x);
    float s1 = d.y * (a.y + uu.y);
    float p0, p1, q0, q1;
    mlp2(s0, w1q, bbq, e0q, e1q, p0, p1);
    mlp2(s1, w1q, bbq, e0q, e1q, q0, q1);
    reinterpret_cast<float4*>(g_t)[i] =
        make_float4(d.x * p0, d.x * p1, d.y * q0, d.y * q1);
    reinterpret_cast<float4*>(g_acc2)[i] = make_float4(0.f, 0.f, 0.f, 0.f);
}

// scatter layer-2 messages: acc2[col] += t[row]; 4 edges per thread
__global__ __launch_bounds__(256) void k_scat2(const int* __restrict__ row,
                                               const int* __restrict__ col, int E) {
    int i = (blockIdx.x * blockDim.x + threadIdx.x) * 4;
    if (i + 3 < E) {
        int4 r = __ldcs(reinterpret_cast<const int4*>(row + i));
        int4 c = __ldcs(reinterpret_cast<const int4*>(col + i));
        float2 t0 = __ldg(&g_t[r.x]);
        float2 t1 = __ldg(&g_t[r.y]);
        float2 t2 = __ldg(&g_t[r.z]);
        float2 t3 = __ldg(&g_t[r.w]);
        red_add_v2(&g_acc2[c.x], t0);
        red_add_v2(&g_acc2[c.y], t1);
        red_add_v2(&g_acc2[c.z], t2);
        red_add_v2(&g_acc2[c.w], t3);
    }
}

// final: out = dis*(acc2 + t) + b2, log_softmax over 2 classes; 2 nodes/thread
__global__ __launch_bounds__(256) void k_out(const float* __restrict__ b2,
                                             float4* __restrict__ out) {
    int i = blockIdx.x * blockDim.x + threadIdx.x;
    if (i >= NN / 2) return;
    float b20 = __ldg(&b2[0]);
    float b21 = __ldg(&b2[1]);
    float2 d = reinterpret_cast<const float2*>(g_dis)[i];
    float4 a = reinterpret_cast<const float4*>(g_acc2)[i];
    float4 t = reinterpret_cast<const float4*>(g_t)[i];
    float o0 = fmaf(d.x, a.x + t.x, b20);
    float o1 = fmaf(d.x, a.y + t.y, b21);
    float o2 = fmaf(d.y, a.z + t.z, b20);
    float o3 = fmaf(d.y, a.w + t.w, b21);
    float m0  = fmaxf(o0, o1);
    float l0  = m0 + log1pf(__expf(fminf(o0, o1) - m0));
    float m1  = fmaxf(o2, o3);
    float l1  = m1 + log1pf(__expf(fminf(o2, o3) - m1));
    out[i] = make_float4(o0 - l0, o1 - l0, o2 - l1, o3 - l1);
}

// ---------------------------------------------------------------------------
extern "C" void kernel_launch(void* const* d_in, const int* in_sizes, int n_in,
                              void* d_out, int out_size) {
    const float* x   = (const float*)d_in[0];
    const int*   ei  = (const int*)d_in[1];
    const float* W1  = (const float*)d_in[2];
    const float* b1  = (const float*)d_in[3];
    const float* W2  = (const float*)d_in[4];
    const float* b2  = (const float*)d_in[5];

    const int E = in_sizes[1] / 2;      // edge_index is [2, E]
    const int* row = ei;                // source
    const int* col = ei + E;            // target

    const int TB = 256;
    const int n4Blocks = (NN / 4 + TB - 1) / TB;
    const int n2Blocks = (NN / 2 + TB - 1) / TB;
    const int edgeBlocks = (E / 4 + TB - 1) / TB;   // 4 edges per thread

    k_zero <<<n4Blocks, TB>>>();
    k_deg  <<<edgeBlocks, TB>>>(col, E);
    k_prep <<<n4Blocks, TB>>>((const float4*)x);
    k_scat1<<<edgeBlocks, TB>>>(row, col, E);
    k_node2<<<n2Blocks, TB>>>((const float4*)W1, (const float4*)b1,
                              (const float4*)W2);
    k_scat2<<<edgeBlocks, TB>>>(row, col, E);
    k_out  <<<n2Blocks, TB>>>(b2, (float4*)d_out);
}

// round 7
// speedup vs baseline: 1.4399x; 1.0059x over previous
#include <cuda_runtime.h>
#include <cstdint>

#define NN 1000000
#define NE 16000000

// ---- scratch (device globals; no allocations allowed) ----
// g_deg is zero at module load; every call re-zeroes it in k_out's tail,
// so each kernel_launch call sees deg==0 at entry (state invariant).
__device__ int    g_deg[NN];
__device__ float  g_dis[NN];
__device__ float  g_u[NN];
__device__ float  g_acc1[NN];
__device__ float2 g_t[NN];
__device__ float2 g_acc2[NN];

// ---- no-return global reductions ----
__device__ __forceinline__ void red_add_u32(int* addr) {
    asm volatile("red.global.add.u32 [%0], 1;" :: "l"(addr) : "memory");
}
__device__ __forceinline__ void red_add_f32(float* addr, float v) {
    asm volatile("red.global.add.f32 [%0], %1;" :: "l"(addr), "f"(v) : "memory");
}
__device__ __forceinline__ void red_add_v2(float2* addr, float2 v) {
    asm volatile("red.global.add.v2.f32 [%0], {%1, %2};"
                 :: "l"(addr), "f"(v.x), "f"(v.y) : "memory");
}

// ---------------------------------------------------------------------------
// degree count over target (col) indices; 4 edges per thread
__global__ __launch_bounds__(256) void k_deg(const int* __restrict__ col, int E) {
    int i = (blockIdx.x * blockDim.x + threadIdx.x) * 4;
    if (i + 3 < E) {
        int4 c = __ldcs(reinterpret_cast<const int4*>(col + i));
        red_add_u32(&g_deg[c.x]);
        red_add_u32(&g_deg[c.y]);
        red_add_u32(&g_deg[c.z]);
        red_add_u32(&g_deg[c.w]);
    }
}

// dis = rsqrt(deg + 1 self-loop); u = dis * x; zero acc1.  4 nodes/thread.
__global__ __launch_bounds__(256) void k_prep(const float4* __restrict__ x4) {
    int i = blockIdx.x * blockDim.x + threadIdx.x;
    if (i >= NN / 4) return;
    int4   dg = reinterpret_cast<const int4*>(g_deg)[i];
    float4 xv = __ldg(&x4[i]);
    float4 d;
    d.x = rsqrtf((float)(dg.x + 1));
    d.y = rsqrtf((float)(dg.y + 1));
    d.z = rsqrtf((float)(dg.z + 1));
    d.w = rsqrtf((float)(dg.w + 1));
    float4 u = make_float4(d.x * xv.x, d.y * xv.y, d.z * xv.z, d.w * xv.w);
    reinterpret_cast<float4*>(g_dis)[i]  = d;
    reinterpret_cast<float4*>(g_u)[i]    = u;
    reinterpret_cast<float4*>(g_acc1)[i] = make_float4(0.f, 0.f, 0.f, 0.f);
}

// scatter layer-1 messages: acc1[col] += u[row]; 4 edges per thread
__global__ __launch_bounds__(256) void k_scat1(const int* __restrict__ row,
                                               const int* __restrict__ col, int E) {
    int i = (blockIdx.x * blockDim.x + threadIdx.x) * 4;
    if (i + 3 < E) {
        int4 r = __ldcs(reinterpret_cast<const int4*>(row + i));
        int4 c = __ldcs(reinterpret_cast<const int4*>(col + i));
        float u0 = __ldg(&g_u[r.x]);
        float u1 = __ldg(&g_u[r.y]);
        float u2 = __ldg(&g_u[r.z]);
        float u3 = __ldg(&g_u[r.w]);
        red_add_f32(&g_acc1[c.x], u0);
        red_add_f32(&g_acc1[c.y], u1);
        red_add_f32(&g_acc1[c.z], u2);
        red_add_f32(&g_acc1[c.w], u3);
    }
}

// per-node MLP, 2 nodes/thread: s -> relu(W1*s+b1) -> @W2 ; t = dis*g; zero acc2
__device__ __forceinline__ void mlp2(float s, const float4* w1q, const float4* bbq,
                                     const float4* e0q, const float4* e1q,
                                     float& g0, float& g1) {
    g0 = 0.0f; g1 = 0.0f;
#pragma unroll
    for (int q = 0; q < 4; q++) {
        float h0 = fmaxf(fmaf(s, w1q[q].x, bbq[q].x), 0.0f);
        float h1 = fmaxf(fmaf(s, w1q[q].y, bbq[q].y), 0.0f);
        float h2 = fmaxf(fmaf(s, w1q[q].z, bbq[q].z), 0.0f);
        float h3 = fmaxf(fmaf(s, w1q[q].w, bbq[q].w), 0.0f);
        g0 = fmaf(h0, e0q[q].x, g0); g1 = fmaf(h0, e0q[q].y, g1);
        g0 = fmaf(h1, e0q[q].z, g0); g1 = fmaf(h1, e0q[q].w, g1);
        g0 = fmaf(h2, e1q[q].x, g0); g1 = fmaf(h2, e1q[q].y, g1);
        g0 = fmaf(h3, e1q[q].z, g0); g1 = fmaf(h3, e1q[q].w, g1);
    }
}

__global__ __launch_bounds__(256) void k_node2(const float4* __restrict__ W1,
                                               const float4* __restrict__ b1,
                                               const float4* __restrict__ W2) {
    int i = blockIdx.x * blockDim.x + threadIdx.x;
    if (i >= NN / 2) return;
    float4 w1q[4], bbq[4], e0q[4], e1q[4];
#pragma unroll
    for (int q = 0; q < 4; q++) {
        w1q[q] = __ldg(&W1[q]);
        bbq[q] = __ldg(&b1[q]);
        e0q[q] = __ldg(&W2[2 * q]);
        e1q[q] = __ldg(&W2[2 * q + 1]);
    }
    float2 d  = reinterpret_cast<const float2*>(g_dis)[i];
    float2 a  = reinterpret_cast<const float2*>(g_acc1)[i];
    float2 uu = reinterpret_cast<const float2*>(g_u)[i];
    float s0 = d.x * (a.x + uu.x);
    float s1 = d.y * (a.y + uu.y);
    float p0, p1, q0, q1;
    mlp2(s0, w1q, bbq, e0q, e1q, p0, p1);
    mlp2(s1, w1q, bbq, e0q, e1q, q0, q1);
    reinterpret_cast<float4*>(g_t)[i] =
        make_float4(d.x * p0, d.x * p1, d.y * q0, d.y * q1);
    reinterpret_cast<float4*>(g_acc2)[i] = make_float4(0.f, 0.f, 0.f, 0.f);
}

// scatter layer-2 messages: acc2[col] += t[row]; 4 edges per thread
__global__ __launch_bounds__(256) void k_scat2(const int* __restrict__ row,
                                               const int* __restrict__ col, int E) {
    int i = (blockIdx.x * blockDim.x + threadIdx.x) * 4;
    if (i + 3 < E) {
        int4 r = __ldcs(reinterpret_cast<const int4*>(row + i));
        int4 c = __ldcs(reinterpret_cast<const int4*>(col + i));
        float2 t0 = __ldg(&g_t[r.x]);
        float2 t1 = __ldg(&g_t[r.y]);
        float2 t2 = __ldg(&g_t[r.z]);
        float2 t3 = __ldg(&g_t[r.w]);
        red_add_v2(&g_acc2[c.x], t0);
        red_add_v2(&g_acc2[c.y], t1);
        red_add_v2(&g_acc2[c.z], t2);
        red_add_v2(&g_acc2[c.w], t3);
    }
}

// final: out = dis*(acc2 + t) + b2, log_softmax over 2 classes; 2 nodes/thread.
// Also re-zeroes g_deg for the next call (graph replay invariant).
__global__ __launch_bounds__(256) void k_out(const float* __restrict__ b2,
                                             float4* __restrict__ out) {
    int i = blockIdx.x * blockDim.x + threadIdx.x;
    if (i >= NN / 2) return;
    float b20 = __ldg(&b2[0]);
    float b21 = __ldg(&b2[1]);
    float2 d = reinterpret_cast<const float2*>(g_dis)[i];
    float4 a = reinterpret_cast<const float4*>(g_acc2)[i];
    float4 t = reinterpret_cast<const float4*>(g_t)[i];
    float o0 = fmaf(d.x, a.x + t.x, b20);
    float o1 = fmaf(d.x, a.y + t.y, b21);
    float o2 = fmaf(d.y, a.z + t.z, b20);
    float o3 = fmaf(d.y, a.w + t.w, b21);
    float m0  = fmaxf(o0, o1);
    float l0  = m0 + log1pf(__expf(fminf(o0, o1) - m0));
    float m1  = fmaxf(o2, o3);
    float l1  = m1 + log1pf(__expf(fminf(o2, o3) - m1));
    out[i] = make_float4(o0 - l0, o1 - l0, o2 - l1, o3 - l1);
    // restore deg=0 for the next replay (2 nodes per thread)
    reinterpret_cast<int2*>(g_deg)[i] = make_int2(0, 0);
}

// ---------------------------------------------------------------------------
extern "C" void kernel_launch(void* const* d_in, const int* in_sizes, int n_in,
                              void* d_out, int out_size) {
    const float* x   = (const float*)d_in[0];
    const int*   ei  = (const int*)d_in[1];
    const float* W1  = (const float*)d_in[2];
    const float* b1  = (const float*)d_in[3];
    const float* W2  = (const float*)d_in[4];
    const float* b2  = (const float*)d_in[5];

    const int E = in_sizes[1] / 2;      // edge_index is [2, E]
    const int* row = ei;                // source
    const int* col = ei + E;            // target

    const int TB = 256;
    const int n4Blocks = (NN / 4 + TB - 1) / TB;
    const int n2Blocks = (NN / 2 + TB - 1) / TB;
    const int edgeBlocks = (E / 4 + TB - 1) / TB;   // 4 edges per thread

    k_deg  <<<edgeBlocks, TB>>>(col, E);
    k_prep <<<n4Blocks, TB>>>((const float4*)x);
    k_scat1<<<edgeBlocks, TB>>>(row, col, E);
    k_node2<<<n2Blocks, TB>>>((const float4*)W1, (const float4*)b1,
                              (const float4*)W2);
    k_scat2<<<edgeBlocks, TB>>>(row, col, E);
    k_out  <<<n2Blocks, TB>>>(b2, (float4*)d_out);
}